// round 1
// baseline (speedup 1.0000x reference)
#include <cuda_runtime.h>
#include <cstdint>
#include <math.h>

// Problem constants (from setup_inputs)
namespace {
constexpr int B_ = 2;
constexpr int C_ = 32;
constexpr int H_ = 128;
constexpr int W_ = 160;
constexpr int D_ = 32;
constexpr int N_ = 4;
constexpr int HW_ = H_ * W_;
}

#define FULLMASK 0xffffffffu

// Scratch (channel-last layouts). __device__ globals: allowed scratch.
__device__ float g_src_t[N_ * B_ * HW_ * C_];  // [v][b][y*W+x][c]
__device__ float g_ref_t[B_ * HW_ * C_];       // [b][y*W+x][c]
__device__ float g_dep_t[B_ * HW_ * D_];       // [b][y*W+x][d]
__device__ float g_rt[B_ * N_ * 12];           // rot(9) + trans(3) per (b,v)

// ---------------------------------------------------------------------------
// Transpose [P][32][HW] -> [P][HW][32]  (32x32 smem tile, padded)
// ---------------------------------------------------------------------------
__global__ void transpose_c32(const float* __restrict__ in, float* __restrict__ out) {
    __shared__ float tile[32][33];
    const int p = blockIdx.z;
    const int hw0 = blockIdx.x * 32;
    const float* ip = in + (size_t)p * 32 * HW_;
    float* op = out + (size_t)p * HW_ * 32;
    const int tx = threadIdx.x, ty = threadIdx.y;
#pragma unroll
    for (int k = 0; k < 32; k += 8)
        tile[ty + k][tx] = ip[(size_t)(ty + k) * HW_ + hw0 + tx];
    __syncthreads();
#pragma unroll
    for (int k = 0; k < 32; k += 8)
        op[(size_t)(hw0 + ty + k) * 32 + tx] = tile[tx][ty + k];
}

// ---------------------------------------------------------------------------
// Projection setup: per (b, v): proj = src_proj_new @ inv(ref_proj_new)
// ---------------------------------------------------------------------------
__device__ void build_new(const float* pm, int b, int vv, float Mo[4][4]) {
    const float* E = pm + (((b * (N_ + 1) + vv) * 2 + 0) * 16);
    const float* K = pm + (((b * (N_ + 1) + vv) * 2 + 1) * 16);
    for (int i = 0; i < 3; i++)
        for (int j = 0; j < 4; j++)
            Mo[i][j] = K[i * 4 + 0] * E[0 + j] + K[i * 4 + 1] * E[4 + j] + K[i * 4 + 2] * E[8 + j];
    for (int j = 0; j < 4; j++) Mo[3][j] = E[12 + j];
}

__global__ void setup_proj(const float* __restrict__ pm) {
    const int t = threadIdx.x;
    if (t >= B_ * N_) return;
    const int b = t / N_, v = t % N_;
    float R[4][4], S[4][4];
    build_new(pm, b, 0, R);
    build_new(pm, b, v + 1, S);
    // Gauss-Jordan inverse of R with partial pivoting
    float M[4][8];
    for (int i = 0; i < 4; i++)
        for (int j = 0; j < 4; j++) { M[i][j] = R[i][j]; M[i][4 + j] = (i == j) ? 1.f : 0.f; }
    for (int c = 0; c < 4; c++) {
        int piv = c;
        for (int r = c + 1; r < 4; r++)
            if (fabsf(M[r][c]) > fabsf(M[piv][c])) piv = r;
        if (piv != c)
            for (int j = 0; j < 8; j++) { float tmp = M[c][j]; M[c][j] = M[piv][j]; M[piv][j] = tmp; }
        const float ip = 1.f / M[c][c];
        for (int j = 0; j < 8; j++) M[c][j] *= ip;
        for (int r = 0; r < 4; r++)
            if (r != c) {
                const float f = M[r][c];
                for (int j = 0; j < 8; j++) M[r][j] -= f * M[c][j];
            }
    }
    float* o = g_rt + (b * N_ + v) * 12;
    for (int i = 0; i < 3; i++)
        for (int j = 0; j < 3; j++)
            o[i * 3 + j] = S[i][0] * M[0][4 + j] + S[i][1] * M[1][4 + j] +
                           S[i][2] * M[2][4 + j] + S[i][3] * M[3][4 + j];
    for (int i = 0; i < 3; i++)
        o[9 + i] = S[i][0] * M[0][7] + S[i][1] * M[1][7] + S[i][2] * M[2][7] + S[i][3] * M[3][7];
}

// ---------------------------------------------------------------------------
// Main kernel: warp per pixel (lane = channel), 8 pixels per 256-thread block.
// Per-warp smem: s[8g][32d] (pad 33), feats[8][32] (pad 33), wsum[32] = 560 fl.
// ---------------------------------------------------------------------------
__global__ __launch_bounds__(256) void stage_main(
    const float* __restrict__ regw, const float* __restrict__ regb,
    float* __restrict__ out_depth, float* __restrict__ out_attn) {
    __shared__ float sm[8 * 560];
    const int lane = threadIdx.x & 31;
    const int wi = threadIdx.x >> 5;
    const int x = blockIdx.x * 8 + wi;
    const int y = blockIdx.y;
    const int b = blockIdx.z;
    float* s_s = sm + wi * 560;        // per-view correlation s[g*33 + d]
    float* f_s = s_s + 264;            // feats accumulator f[g*33 + d]
    float* w_s = s_s + 528;            // wsum[d]
    const int pix = y * W_ + x;
    const size_t pb32 = ((size_t)b * HW_ + pix) * 32;
    const float refc = g_ref_t[pb32 + lane];  // ref channel value (lane = channel)
    const float dl = g_dep_t[pb32 + lane];    // depth hypo (lane = depth)

#pragma unroll
    for (int g = 0; g < 8; g++) f_s[g * 33 + lane] = 0.f;
    w_s[lane] = 1e-8f;

    const float fx = (float)x, fy = (float)y;

    for (int v = 0; v < N_; v++) {
        const float* rt = g_rt + (b * N_ + v) * 12;
        const float r00 = rt[0], r01 = rt[1], r02 = rt[2];
        const float r10 = rt[3], r11 = rt[4], r12 = rt[5];
        const float r20 = rt[6], r21 = rt[7], r22 = rt[8];
        const float t0 = rt[9], t1 = rt[10], t2 = rt[11];
        const float rx = r00 * fx + r01 * fy + r02;
        const float ry = r10 * fx + r11 * fy + r12;
        const float rz = r20 * fx + r21 * fy + r22;
        const float* sv = g_src_t + ((size_t)(v * B_ + b)) * HW_ * 32;
        __syncwarp();
#pragma unroll 4
        for (int d = 0; d < D_; d++) {
            const float dep = __shfl_sync(FULLMASK, dl, d);
            float pz = rz * dep + t2;
            pz = (pz == 0.f) ? 1e-9f : pz;
            const float gx = __fdiv_rn(rx * dep + t0, pz);
            const float gy = __fdiv_rn(ry * dep + t1, pz);
            const float x0f = floorf(gx), y0f = floorf(gy);
            const float wx = gx - x0f, wy = gy - y0f;
            const int ix = (int)x0f, iy = (int)y0f;
            const bool vx0 = (x0f >= 0.f) && (x0f <= (float)(W_ - 1));
            const bool vx1 = (x0f >= -1.f) && (x0f <= (float)(W_ - 2));
            const bool vy0 = (y0f >= 0.f) && (y0f <= (float)(H_ - 1));
            const bool vy1 = (y0f >= -1.f) && (y0f <= (float)(H_ - 2));
            const float* p00 = sv + ((long)iy * W_ + ix) * 32 + lane;
            const float v00 = (vx0 && vy0) ? __ldg(p00) : 0.f;
            const float v10 = (vx1 && vy0) ? __ldg(p00 + 32) : 0.f;
            const float v01 = (vx0 && vy1) ? __ldg(p00 + W_ * 32) : 0.f;
            const float v11 = (vx1 && vy1) ? __ldg(p00 + W_ * 32 + 32) : 0.f;
            const float samp = v00 * (1.f - wx) * (1.f - wy) + v10 * wx * (1.f - wy) +
                               v01 * (1.f - wx) * wy + v11 * wx * wy;
            float sc = samp * refc;
            sc += __shfl_xor_sync(FULLMASK, sc, 1);
            sc += __shfl_xor_sync(FULLMASK, sc, 2);
            if ((lane & 3) == 0) s_s[(lane >> 2) * 33 + d] = sc * 0.25f;  // mean over 4 ch
        }
        __syncwarp();
        // per-view softmax over depth (lane = depth)
        float ssum = 0.f;
#pragma unroll
        for (int g = 0; g < 8; g++) ssum += s_s[g * 33 + lane];
        const float logit = ssum * 0.5f;  // / attn_temp(2.0)
        float mx = logit;
#pragma unroll
        for (int o = 16; o > 0; o >>= 1) mx = fmaxf(mx, __shfl_xor_sync(FULLMASK, mx, o));
        const float e = expf(logit - mx);
        float tot = e;
#pragma unroll
        for (int o = 16; o > 0; o >>= 1) tot += __shfl_xor_sync(FULLMASK, tot, o);
        const float w = __fdiv_rn(e, tot) * 0.17677669529663687f;  // / sqrt(C)
        w_s[lane] += w;
#pragma unroll
        for (int g = 0; g < 8; g++) f_s[g * 33 + lane] += w * s_s[g * 33 + lane];
    }

    // Final: logits = sum_g (feats/wsum)*reg_w + reg_b, softmax, argmax
    const float wden = w_s[lane];
    float acc = 0.f;
#pragma unroll
    for (int g = 0; g < 8; g++)
        acc += __fdiv_rn(f_s[g * 33 + lane], wden) * __ldg(regw + g);
    const float logit = acc + __ldg(regb);
    float mx = logit;
#pragma unroll
    for (int o = 16; o > 0; o >>= 1) mx = fmaxf(mx, __shfl_xor_sync(FULLMASK, mx, o));
    const float e = expf(logit - mx);
    float tot = e;
#pragma unroll
    for (int o = 16; o > 0; o >>= 1) tot += __shfl_xor_sync(FULLMASK, tot, o);
    const float attn = __fdiv_rn(e, tot);

    // argmax with first-occurrence tie-break
    float bv = attn;
    int bi = lane;
#pragma unroll
    for (int o = 16; o > 0; o >>= 1) {
        const float ov = __shfl_xor_sync(FULLMASK, bv, o);
        const int oi = __shfl_xor_sync(FULLMASK, bi, o);
        if (ov > bv || (ov == bv && oi < bi)) { bv = ov; bi = oi; }
    }
    const float dsel = __shfl_sync(FULLMASK, dl, bi);
    if (lane == 0) out_depth[(b * H_ + y) * W_ + x] = dsel;

    // Stage attn in smem, write coalesced (d-major across the 8 block pixels)
    w_s[lane] = attn;
    __syncthreads();
    const int t = threadIdx.x;
    const int dd = t >> 3, wj = t & 7;
    out_attn[(((size_t)b * D_ + dd) * H_ + y) * W_ + blockIdx.x * 8 + wj] =
        sm[wj * 560 + 528 + dd];
}

// ---------------------------------------------------------------------------
extern "C" void kernel_launch(void* const* d_in, const int* in_sizes, int n_in,
                              void* d_out, int out_size) {
    const float* ref = (const float*)d_in[0];   // (B,C,H,W)
    const float* src = (const float*)d_in[1];   // (N,B,C,H,W)
    const float* pm  = (const float*)d_in[2];   // (B,5,2,4,4)
    const float* dep = (const float*)d_in[3];   // (B,D,H,W)
    const float* rw  = (const float*)d_in[4];   // (8,)
    const float* rb  = (const float*)d_in[5];   // (1,)
    float* out_depth = (float*)d_out;
    float* out_attn  = out_depth + (size_t)B_ * HW_;

    float *g_src_p, *g_ref_p, *g_dep_p;
    cudaGetSymbolAddress((void**)&g_src_p, g_src_t);
    cudaGetSymbolAddress((void**)&g_ref_p, g_ref_t);
    cudaGetSymbolAddress((void**)&g_dep_p, g_dep_t);

    dim3 tb(32, 8);
    transpose_c32<<<dim3(HW_ / 32, 1, N_ * B_), tb>>>(src, g_src_p);
    transpose_c32<<<dim3(HW_ / 32, 1, B_), tb>>>(ref, g_ref_p);
    transpose_c32<<<dim3(HW_ / 32, 1, B_), tb>>>(dep, g_dep_p);
    setup_proj<<<1, 32>>>(pm);
    stage_main<<<dim3(W_ / 8, H_, B_), 256>>>(rw, rb, out_depth, out_attn);
}

// round 2
// speedup vs baseline: 1.8467x; 1.8467x over previous
#include <cuda_runtime.h>
#include <cstdint>
#include <math.h>

namespace {
constexpr int B_ = 2;
constexpr int C_ = 32;
constexpr int H_ = 128;
constexpr int W_ = 160;
constexpr int D_ = 32;
constexpr int N_ = 4;
constexpr int HW_ = H_ * W_;
}

#define FULLMASK 0xffffffffu

__device__ float g_src_t[N_ * B_ * HW_ * C_];  // [v][b][pix][c]
__device__ float g_ref_t[B_ * HW_ * C_];       // [b][pix][c]
__device__ float g_dep_t[B_ * HW_ * D_];       // [b][pix][d]
__device__ float g_rt[B_ * N_ * 12];           // rot(9) + trans(3)

// ---------------------------------------------------------------------------
__global__ void transpose_c32(const float* __restrict__ in, float* __restrict__ out) {
    __shared__ float tile[32][33];
    const int p = blockIdx.z;
    const int hw0 = blockIdx.x * 32;
    const float* ip = in + (size_t)p * 32 * HW_;
    float* op = out + (size_t)p * HW_ * 32;
    const int tx = threadIdx.x, ty = threadIdx.y;
#pragma unroll
    for (int k = 0; k < 32; k += 8)
        tile[ty + k][tx] = ip[(size_t)(ty + k) * HW_ + hw0 + tx];
    __syncthreads();
#pragma unroll
    for (int k = 0; k < 32; k += 8)
        op[(size_t)(hw0 + ty + k) * 32 + tx] = tile[tx][ty + k];
}

// ---------------------------------------------------------------------------
__device__ void build_new(const float* pm, int b, int vv, float Mo[4][4]) {
    const float* E = pm + (((b * (N_ + 1) + vv) * 2 + 0) * 16);
    const float* K = pm + (((b * (N_ + 1) + vv) * 2 + 1) * 16);
    for (int i = 0; i < 3; i++)
        for (int j = 0; j < 4; j++)
            Mo[i][j] = K[i * 4 + 0] * E[0 + j] + K[i * 4 + 1] * E[4 + j] + K[i * 4 + 2] * E[8 + j];
    for (int j = 0; j < 4; j++) Mo[3][j] = E[12 + j];
}

__global__ void setup_proj(const float* __restrict__ pm) {
    const int t = threadIdx.x;
    if (t >= B_ * N_) return;
    const int b = t / N_, v = t % N_;
    float R[4][4], S[4][4];
    build_new(pm, b, 0, R);
    build_new(pm, b, v + 1, S);
    float M[4][8];
    for (int i = 0; i < 4; i++)
        for (int j = 0; j < 4; j++) { M[i][j] = R[i][j]; M[i][4 + j] = (i == j) ? 1.f : 0.f; }
    for (int c = 0; c < 4; c++) {
        int piv = c;
        for (int r = c + 1; r < 4; r++)
            if (fabsf(M[r][c]) > fabsf(M[piv][c])) piv = r;
        if (piv != c)
            for (int j = 0; j < 8; j++) { float tmp = M[c][j]; M[c][j] = M[piv][j]; M[piv][j] = tmp; }
        const float ip = 1.f / M[c][c];
        for (int j = 0; j < 8; j++) M[c][j] *= ip;
        for (int r = 0; r < 4; r++)
            if (r != c) {
                const float f = M[r][c];
                for (int j = 0; j < 8; j++) M[r][j] -= f * M[c][j];
            }
    }
    float* o = g_rt + (b * N_ + v) * 12;
    for (int i = 0; i < 3; i++)
        for (int j = 0; j < 3; j++)
            o[i * 3 + j] = S[i][0] * M[0][4 + j] + S[i][1] * M[1][4 + j] +
                           S[i][2] * M[2][4 + j] + S[i][3] * M[3][4 + j];
    for (int i = 0; i < 3; i++)
        o[9 + i] = S[i][0] * M[0][7] + S[i][1] * M[1][7] + S[i][2] * M[2][7] + S[i][3] * M[3][7];
}

// ---------------------------------------------------------------------------
// Warp per pixel. Lane decomposition in gather loop:
//   cg = lane&7 (channel group, 4 ch each), tx=(lane>>3)&1, ty=(lane>>4)&1 (tap)
// One LDG.128 per lane per depth covers 4 taps x 32 channels per warp.
// Coordinates precomputed per view with lane = depth (divs off the load path).
// ---------------------------------------------------------------------------
__global__ __launch_bounds__(256) void stage_main(
    const float* __restrict__ regw, const float* __restrict__ regb,
    float* __restrict__ out_depth, float* __restrict__ out_attn) {
    __shared__ float sm[8 * 560];
    const int lane = threadIdx.x & 31;
    const int wi = threadIdx.x >> 5;
    const int x = blockIdx.x * 8 + wi;
    const int y = blockIdx.y;
    const int b = blockIdx.z;
    float* s_s = sm + wi * 560;        // s[g*33 + d]
    float* f_s = s_s + 264;            // f[g*33 + d]
    float* w_s = s_s + 528;            // wsum[d] / attn staging
    const int pix = y * W_ + x;
    const size_t pb32 = ((size_t)b * HW_ + pix) * 32;

    const int cg = lane & 7;
    const int tx = (lane >> 3) & 1;
    const int ty = (lane >> 4) & 1;
    const float4 refv = *(const float4*)(g_ref_t + pb32 + cg * 4);
    const float dl = g_dep_t[pb32 + lane];  // lane = depth index

#pragma unroll
    for (int g = 0; g < 8; g++) f_s[g * 33 + lane] = 0.f;
    w_s[lane] = 1e-8f;

    const float fx = (float)x, fy = (float)y;

    for (int v = 0; v < N_; v++) {
        const float* rt = g_rt + (b * N_ + v) * 12;
        const float rx = rt[0] * fx + rt[1] * fy + rt[2];
        const float ry = rt[3] * fx + rt[4] * fy + rt[5];
        const float rz = rt[6] * fx + rt[7] * fy + rt[8];
        const float t0 = rt[9], t1 = rt[10], t2 = rt[11];
        const float* sv = g_src_t + ((size_t)(v * B_ + b)) * HW_ * 32;

        // --- per-lane (lane = my depth) coordinate computation ---
        float pz = rz * dl + t2;
        pz = (pz == 0.f) ? 1e-9f : pz;
        const float gx = __fdiv_rn(rx * dl + t0, pz);
        const float gy = __fdiv_rn(ry * dl + t1, pz);
        const float x0f = floorf(gx), y0f = floorf(gy);
        const float mywx = gx - x0f, mywy = gy - y0f;
        // clamp keeps ints sane; clamped values remain invalid for all taps
        const int myix = (int)fminf(fmaxf(x0f, -2.f), (float)(W_ + 1));
        const int myiy = (int)fminf(fmaxf(y0f, -2.f), (float)(H_ + 1));

        __syncwarp();
#pragma unroll 4
        for (int d = 0; d < D_; d++) {
            const int ix = __shfl_sync(FULLMASK, myix, d);
            const int iy = __shfl_sync(FULLMASK, myiy, d);
            const float wx = __shfl_sync(FULLMASK, mywx, d);
            const float wy = __shfl_sync(FULLMASK, mywy, d);
            const int px = ix + tx, py = iy + ty;
            const bool valid = (px >= 0) & (px <= W_ - 1) & (py >= 0) & (py <= H_ - 1);
            const float wt = (tx ? wx : 1.f - wx) * (ty ? wy : 1.f - wy);
            float4 vv = make_float4(0.f, 0.f, 0.f, 0.f);
            if (valid) vv = __ldg((const float4*)(sv + ((long)py * W_ + px) * 32 + cg * 4));
            float p = wt * (vv.x * refv.x + vv.y * refv.y + vv.z * refv.z + vv.w * refv.w);
            p += __shfl_xor_sync(FULLMASK, p, 8);
            p += __shfl_xor_sync(FULLMASK, p, 16);
            if (lane < 8) s_s[lane * 33 + d] = p * 0.25f;  // group mean over 4 ch
        }
        __syncwarp();

        // per-view softmax over depth (lane = depth)
        float ssum = 0.f;
#pragma unroll
        for (int g = 0; g < 8; g++) ssum += s_s[g * 33 + lane];
        const float logit = ssum * 0.5f;
        float mx = logit;
#pragma unroll
        for (int o = 16; o > 0; o >>= 1) mx = fmaxf(mx, __shfl_xor_sync(FULLMASK, mx, o));
        const float e = expf(logit - mx);
        float tot = e;
#pragma unroll
        for (int o = 16; o > 0; o >>= 1) tot += __shfl_xor_sync(FULLMASK, tot, o);
        const float w = __fdiv_rn(e, tot) * 0.17677669529663687f;  // / sqrt(C)
        w_s[lane] += w;
#pragma unroll
        for (int g = 0; g < 8; g++) f_s[g * 33 + lane] += w * s_s[g * 33 + lane];
    }

    // Final regression + softmax + argmax (lane = depth)
    const float wden = w_s[lane];
    float acc = 0.f;
#pragma unroll
    for (int g = 0; g < 8; g++)
        acc += __fdiv_rn(f_s[g * 33 + lane], wden) * __ldg(regw + g);
    const float logit = acc + __ldg(regb);
    float mx = logit;
#pragma unroll
    for (int o = 16; o > 0; o >>= 1) mx = fmaxf(mx, __shfl_xor_sync(FULLMASK, mx, o));
    const float e = expf(logit - mx);
    float tot = e;
#pragma unroll
    for (int o = 16; o > 0; o >>= 1) tot += __shfl_xor_sync(FULLMASK, tot, o);
    const float attn = __fdiv_rn(e, tot);

    float bv = attn;
    int bi = lane;
#pragma unroll
    for (int o = 16; o > 0; o >>= 1) {
        const float ov = __shfl_xor_sync(FULLMASK, bv, o);
        const int oi = __shfl_xor_sync(FULLMASK, bi, o);
        if (ov > bv || (ov == bv && oi < bi)) { bv = ov; bi = oi; }
    }
    const float dsel = __shfl_sync(FULLMASK, dl, bi);
    if (lane == 0) out_depth[(b * H_ + y) * W_ + x] = dsel;

    w_s[lane] = attn;
    __syncthreads();
    const int t = threadIdx.x;
    const int dd = t >> 3, wj = t & 7;
    out_attn[(((size_t)b * D_ + dd) * H_ + y) * W_ + blockIdx.x * 8 + wj] =
        sm[wj * 560 + 528 + dd];
}

// ---------------------------------------------------------------------------
extern "C" void kernel_launch(void* const* d_in, const int* in_sizes, int n_in,
                              void* d_out, int out_size) {
    const float* ref = (const float*)d_in[0];
    const float* src = (const float*)d_in[1];
    const float* pm  = (const float*)d_in[2];
    const float* dep = (const float*)d_in[3];
    const float* rw  = (const float*)d_in[4];
    const float* rb  = (const float*)d_in[5];
    float* out_depth = (float*)d_out;
    float* out_attn  = out_depth + (size_t)B_ * HW_;

    float *g_src_p, *g_ref_p, *g_dep_p;
    cudaGetSymbolAddress((void**)&g_src_p, g_src_t);
    cudaGetSymbolAddress((void**)&g_ref_p, g_ref_t);
    cudaGetSymbolAddress((void**)&g_dep_p, g_dep_t);

    dim3 tb(32, 8);
    transpose_c32<<<dim3(HW_ / 32, 1, N_ * B_), tb>>>(src, g_src_p);
    transpose_c32<<<dim3(HW_ / 32, 1, B_), tb>>>(ref, g_ref_p);
    transpose_c32<<<dim3(HW_ / 32, 1, B_), tb>>>(dep, g_dep_p);
    setup_proj<<<1, 32>>>(pm);
    stage_main<<<dim3(W_ / 8, H_, B_), 256>>>(rw, rb, out_depth, out_attn);
}